// round 15
// baseline (speedup 1.0000x reference)
#include <cuda_runtime.h>
#include <cuda_bf16.h>
#include <cstdint>
#include <cstddef>

// Problem constants
#define T_STEPS 784
#define NBATCH  128
#define HID     512
#define OUTC    10
#define DECAY   0.2f
#define THRESH  0.5f
#define KDIM    512

// GEMM tiling (reverted to proven R13 config: 128x128, 2 CTAs/SM)
#define BM 128
#define BN 128
#define BK 64
#define ROWB 144u              // smem bytes per row: 64 bf16 (128B) + 16B pad
#define TILEB (128u * ROWB)    // 18432 B
#define STAGEB (3u * TILEB)    // A + Bh + Bl per stage
#define GEMM_SMEM (2u * STAGEB)

// Recurrence pipelining
#define UNR 16                 // 784 = 49 * 16
#define NBLK (T_STEPS / UNR)   // 49
#define NWORDS 25              // ceil(784/32)

// Packed spikes: 512 bits per (t,n) row = 16 words = 64 bytes
#define WPR 16
#define SEQ_ELEMS ((size_t)T_STEPS * NBATCH * HID)
__device__ uint32_t g_S1p[(size_t)T_STEPS * NBATCH * WPR];
__device__ uint32_t g_S2p[(size_t)T_STEPS * NBATCH * WPR];
__device__ float    g_C  [SEQ_ELEMS];        // GEMM output [t][n][j] fp32 dense
__device__ __nv_bfloat16 g_W2h[HID*HID], g_W2l[HID*HID];
__device__ __nv_bfloat16 g_W3h[HID*HID], g_W3l[HID*HID];
__device__ uint32_t g_mkb[3][NWORDS * HID];  // bit-packed masks

// ---------------------------------------------------------------------------
// PTX helpers
// ---------------------------------------------------------------------------
__device__ __forceinline__ uint32_t smem_u32(const void* p){
    uint32_t a;
    asm("{ .reg .u64 t; cvta.to.shared.u64 t, %1; cvt.u32.u64 %0, t; }" : "=r"(a) : "l"(p));
    return a;
}
__device__ __forceinline__ void cp16(uint32_t saddr, const void* gaddr){
    asm volatile("cp.async.cg.shared.global [%0], [%1], 16;" :: "r"(saddr), "l"(gaddr));
}
__device__ __forceinline__ void ldsm4(uint32_t* r, uint32_t addr){
    asm volatile("ldmatrix.sync.aligned.m8n8.x4.shared.b16 {%0,%1,%2,%3}, [%4];"
        : "=r"(r[0]), "=r"(r[1]), "=r"(r[2]), "=r"(r[3]) : "r"(addr));
}
__device__ __forceinline__ void mma_bf16(float* c, const uint32_t* a, const uint32_t* b){
    asm volatile(
        "mma.sync.aligned.m16n8k16.row.col.f32.bf16.bf16.f32 "
        "{%0,%1,%2,%3}, {%4,%5,%6,%7}, {%8,%9}, {%0,%1,%2,%3};"
        : "+f"(c[0]), "+f"(c[1]), "+f"(c[2]), "+f"(c[3])
        : "r"(a[0]), "r"(a[1]), "r"(a[2]), "r"(a[3]), "r"(b[0]), "r"(b[1]));
}

// ---------------------------------------------------------------------------
// Weight split: W -> hi(bf16) + lo(bf16)
// ---------------------------------------------------------------------------
__global__ void split_kernel(const float* __restrict__ W2, const float* __restrict__ W3){
    int idx = blockIdx.x * blockDim.x + threadIdx.x;
    if (idx < HID * HID){
        float w = W2[idx];
        __nv_bfloat16 h = __float2bfloat16(w);
        g_W2h[idx] = h;
        g_W2l[idx] = __float2bfloat16(w - __bfloat162float(h));
        w = W3[idx];
        h = __float2bfloat16(w);
        g_W3h[idx] = h;
        g_W3l[idx] = __float2bfloat16(w - __bfloat162float(h));
    }
}

// ---------------------------------------------------------------------------
// Mask bit-pack: [H][T] floats -> [NWORDS][H] words
// ---------------------------------------------------------------------------
__global__ void maskbits_kernel(const float* __restrict__ m1,
                                const float* __restrict__ m2,
                                const float* __restrict__ m3)
{
    const int w = blockIdx.x;
    const int l = blockIdx.y;
    const int j = threadIdx.x;
    const float* __restrict__ src = (l == 0) ? m1 : (l == 1) ? m2 : m3;
    uint32_t bits = 0;
    #pragma unroll
    for (int b = 0; b < 32; ++b){
        const int t = w * 32 + b;
        if (t < T_STEPS && src[(size_t)j * T_STEPS + t] != 0.f) bits |= (1u << b);
    }
    g_mkb[l][w * HID + j] = bits;
}

// ---------------------------------------------------------------------------
// Layer-1 recurrence (unchanged from R13)
// ---------------------------------------------------------------------------
__global__ void layer1_kernel(const float* __restrict__ x,
                              const float* __restrict__ W1,
                              const float* __restrict__ b1,
                              float* __restrict__ fr1)
{
    const int n = blockIdx.x;
    const int i = blockIdx.y * 128 + threadIdx.x;
    const int lane = threadIdx.x & 31;
    const float w = W1[i];
    const float b = b1[i];
    const float* __restrict__ xr = x + (size_t)n * T_STEPS;
    const uint32_t* __restrict__ mkb = g_mkb[0];
    uint32_t* __restrict__ pOut = g_S1p + (size_t)n * WPR
                                + (blockIdx.y * 4) + (threadIdx.x >> 5);
    const size_t pstr = (size_t)NBATCH * WPR;

    uint32_t mcur = mkb[i];
    uint32_t mnxt = mkb[HID + i];

    float xb[2][UNR];
    #pragma unroll
    for (int u = 0; u < UNR; ++u) xb[0][u] = xr[u];

    float mem = 0.f, spike = 0.f, ss = 0.f;
    for (int tc = 0; tc < NBLK; ++tc){
        const int cur = tc & 1, nxt = cur ^ 1;
        const int tb = tc * UNR;
        if (tc + 1 < NBLK){
            #pragma unroll
            for (int u = 0; u < UNR; ++u) xb[nxt][u] = xr[tb + UNR + u];
        }
        const uint32_t bits16 = (tc & 1) ? (mcur >> 16) : mcur;
        #pragma unroll
        for (int u = 0; u < UNR; ++u){
            const bool on = (bits16 >> u) & 1u;
            const float dec = (spike != 0.f) ? 0.f : mem * DECAY;
            const float nm = dec + xb[cur][u] * w + b;
            if (on) mem = nm;
            const float spk = (mem > THRESH && on) ? 1.f : 0.f;
            const unsigned bal = __ballot_sync(0xffffffffu, spk != 0.f);
            if (lane == 0) pOut[(size_t)(tb + u) * pstr] = bal;
            ss += spk;
            spike = spk;
        }
        if (tc & 1){
            mcur = mnxt;
            const int wi = (tc >> 1) + 2;
            if (wi < NWORDS) mnxt = mkb[wi * HID + i];
        }
    }
    fr1[n * HID + i] = ss * (1.f / (float)T_STEPS);
}

// ---------------------------------------------------------------------------
// bf16 HMMA GEMM, 128x128 tile (2 CTAs/SM). A-bit loads pipelined 2 chunks
// ahead through registers — expansion never waits on global memory.
// MMA order identical to R13 -> rel_err invariant.
// ---------------------------------------------------------------------------
__global__ void __launch_bounds__(256, 2)
gemm_bf16(int which)
{
    extern __shared__ char smem[];
    const uint8_t* __restrict__ Ap = (const uint8_t*)(which ? g_S2p : g_S1p);
    const __nv_bfloat16* __restrict__ Bh = which ? g_W3h : g_W2h;
    const __nv_bfloat16* __restrict__ Bl = which ? g_W3l : g_W2l;

    const uint32_t sb = smem_u32(smem);
    const int tid  = threadIdx.x;
    const int lane = tid & 31;
    const int wrp  = tid >> 5;
    const int wm   = wrp & 1;          // 2 warp-rows of 64
    const int wn   = wrp >> 1;         // 4 warp-cols of 32
    const int n0 = blockIdx.x * BN;
    const int m0 = blockIdx.y * BM;

    // A-bit register pipeline (2 stages x 4 bytes)
    uint8_t bitsReg[2][4];
    auto fetch_bits = [&](int c, uint8_t* dst){
        #pragma unroll
        for (int i = 0; i < 4; ++i){
            const int q   = tid + 256 * i;
            const int row = q >> 3;
            const int kc  = q & 7;
            dst[i] = __ldg(Ap + (size_t)(m0 + row) * 64 + (size_t)c * 8 + kc);
        }
    };

    auto load_stage = [&](int st, int c, const uint8_t* bitsArr){
        const uint32_t base = sb + (uint32_t)st * STAGEB;
        char* abase = smem + (size_t)st * STAGEB;
        // B cp.asyncs (independent of bits)
        #pragma unroll
        for (int i = 0; i < 4; ++i){
            const int q   = tid + 256 * i;
            const int row = q >> 3;
            const int kc  = q & 7;
            const uint32_t soff = (uint32_t)row * ROWB + (uint32_t)kc * 16u;
            const size_t gk = (size_t)c * BK + (size_t)kc * 8;
            cp16(base + TILEB + soff,     Bh + (size_t)(n0 + row) * KDIM + gk);
            cp16(base + 2u*TILEB + soff,  Bl + (size_t)(n0 + row) * KDIM + gk);
        }
        // Expand prefetched A bits -> bf16 smem (no global dependency here)
        #pragma unroll
        for (int i = 0; i < 4; ++i){
            const int q   = tid + 256 * i;
            const int row = q >> 3;
            const int kc  = q & 7;
            const uint32_t soff = (uint32_t)row * ROWB + (uint32_t)kc * 16u;
            const uint8_t bits = bitsArr[i];
            uint4 v;
            v.x = ((bits &   1u) ? 0x3F80u : 0u) | ((bits &   2u) ? 0x3F800000u : 0u);
            v.y = ((bits &   4u) ? 0x3F80u : 0u) | ((bits &   8u) ? 0x3F800000u : 0u);
            v.z = ((bits &  16u) ? 0x3F80u : 0u) | ((bits &  32u) ? 0x3F800000u : 0u);
            v.w = ((bits &  64u) ? 0x3F80u : 0u) | ((bits & 128u) ? 0x3F800000u : 0u);
            *(uint4*)(abase + soff) = v;
        }
        asm volatile("cp.async.commit_group;" ::: "memory");
    };

    float acc[4][4][4];
    #pragma unroll
    for (int mi = 0; mi < 4; ++mi)
        #pragma unroll
        for (int ni = 0; ni < 4; ++ni)
            #pragma unroll
            for (int q = 0; q < 4; ++q) acc[mi][ni][q] = 0.f;

    const uint32_t aOff = (uint32_t)(wm * 64 + (lane & 15)) * ROWB
                        + (uint32_t)((lane >> 4) << 3) * 2u;
    const uint32_t bOff = (uint32_t)(wn * 32 + ((lane >> 4) << 3) + (lane & 7)) * ROWB
                        + (uint32_t)(((lane >> 3) & 1) << 4);

    // Prologue: bits for chunks 0 and 1, then build stage 0.
    fetch_bits(0, bitsReg[0]);
    fetch_bits(1, bitsReg[1]);
    load_stage(0, 0, bitsReg[0]);

    const int NC = KDIM / BK;   // 8
    for (int c = 0; c < NC; ++c){
        if (c + 1 < NC){
            load_stage((c + 1) & 1, c + 1, bitsReg[(c + 1) & 1]);
            if (c + 2 < NC) fetch_bits(c + 2, bitsReg[c & 1]);  // lands during compute(c)
            asm volatile("cp.async.wait_group 1;" ::: "memory");
        } else {
            asm volatile("cp.async.wait_group 0;" ::: "memory");
        }
        __syncthreads();

        const uint32_t base = sb + (uint32_t)(c & 1) * STAGEB;
        const uint32_t aB = base + aOff;
        const uint32_t hB = base + TILEB + bOff;
        const uint32_t lB = base + 2u*TILEB + bOff;

        #pragma unroll
        for (int k16 = 0; k16 < 4; ++k16){
            uint32_t a[4][4], bh[2][4], bl[2][4];
            #pragma unroll
            for (int mi = 0; mi < 4; ++mi)
                ldsm4(a[mi], aB + (uint32_t)(mi * 16) * ROWB + (uint32_t)k16 * 32u);
            #pragma unroll
            for (int p = 0; p < 2; ++p){
                ldsm4(bh[p], hB + (uint32_t)(p * 16) * ROWB + (uint32_t)k16 * 32u);
                ldsm4(bl[p], lB + (uint32_t)(p * 16) * ROWB + (uint32_t)k16 * 32u);
            }
            #pragma unroll
            for (int mi = 0; mi < 4; ++mi)
                #pragma unroll
                for (int ni = 0; ni < 4; ++ni){
                    mma_bf16(acc[mi][ni], a[mi], &bh[ni >> 1][(ni & 1) * 2]);
                    mma_bf16(acc[mi][ni], a[mi], &bl[ni >> 1][(ni & 1) * 2]);
                }
        }
        __syncthreads();
    }

    const int rbase = m0 + wm * 64 + (lane >> 2);
    const int cbase = n0 + wn * 32 + (lane & 3) * 2;
    #pragma unroll
    for (int mi = 0; mi < 4; ++mi){
        #pragma unroll
        for (int ni = 0; ni < 4; ++ni){
            float* p0 = g_C + (size_t)(rbase + mi * 16) * HID + cbase + ni * 8;
            float* p1 = p0 + 8 * HID;
            *(float2*)p0 = make_float2(acc[mi][ni][0], acc[mi][ni][1]);
            *(float2*)p1 = make_float2(acc[mi][ni][2], acc[mi][ni][3]);
        }
    }
}

// ---------------------------------------------------------------------------
// Layer-2/3 recurrence (unchanged from R13: 3-buffer 2-ahead prefetch)
// ---------------------------------------------------------------------------
__global__ void layerR_kernel(const float* __restrict__ bvec,
                              float* __restrict__ fr,
                              int maskSel, int layer)
{
    const int n = blockIdx.x;
    const int j = blockIdx.y * 128 + threadIdx.x;
    const int lane = threadIdx.x & 31;
    const float bj = bvec[j];
    const uint32_t* __restrict__ mkb = g_mkb[maskSel];
    const size_t cstr = (size_t)NBATCH * HID;
    const float* __restrict__ cPtr = g_C + (size_t)n * HID + j;
    uint32_t* __restrict__ pOut = g_S2p + (size_t)n * WPR
                                + (blockIdx.y * 4) + (threadIdx.x >> 5);
    const size_t pstr = (size_t)NBATCH * WPR;

    uint32_t mcur = mkb[j];
    uint32_t mnxt = mkb[HID + j];

    float cb[3][UNR];
    #pragma unroll
    for (int u = 0; u < UNR; ++u) cb[0][u] = cPtr[(size_t)u * cstr];
    #pragma unroll
    for (int u = 0; u < UNR; ++u) cb[1][u] = cPtr[(size_t)(UNR + u) * cstr];

    float mem = 0.f, spike = 0.f, ss = 0.f;
    #pragma unroll 3
    for (int tc = 0; tc < NBLK; ++tc){
        const int s0 = tc % 3;
        const int tb = tc * UNR;
        if (tc + 2 < NBLK){
            const int s2 = (tc + 2) % 3;
            #pragma unroll
            for (int u = 0; u < UNR; ++u)
                cb[s2][u] = cPtr[(size_t)(tb + 2 * UNR + u) * cstr];
        }
        const uint32_t bits16 = (tc & 1) ? (mcur >> 16) : mcur;
        #pragma unroll
        for (int u = 0; u < UNR; ++u){
            const bool on = (bits16 >> u) & 1u;
            const float dec = (spike != 0.f) ? 0.f : mem * DECAY;
            const float nm = dec + cb[s0][u] + bj;
            if (on) mem = nm;
            const float spk = (mem > THRESH && on) ? 1.f : 0.f;
            if (layer == 2){
                const unsigned bal = __ballot_sync(0xffffffffu, spk != 0.f);
                if (lane == 0) pOut[(size_t)(tb + u) * pstr] = bal;
            }
            ss += spk;
            spike = spk;
        }
        if (tc & 1){
            mcur = mnxt;
            const int wi = (tc >> 1) + 2;
            if (wi < NWORDS) mnxt = mkb[wi * HID + j];
        }
    }
    fr[n * HID + j] = ss * (1.f / (float)T_STEPS);
}

// ---------------------------------------------------------------------------
// Fused head + layer_fr kernel.
// ---------------------------------------------------------------------------
__global__ void tail_kernel(const float* __restrict__ fr_all,
                            const float* __restrict__ W4,
                            const float* __restrict__ b4,
                            float* __restrict__ outputs,
                            float* __restrict__ out3)
{
    if (blockIdx.x < NBATCH){
        const int n = blockIdx.x;
        const int warp = threadIdx.x >> 5;
        const int lane = threadIdx.x & 31;
        if (warp >= OUTC) return;
        const float* __restrict__ f = fr_all + 2 * (NBATCH * HID) + (size_t)n * HID;
        const float* __restrict__ w = W4 + (size_t)warp * HID;
        float s = 0.f;
        for (int j = lane; j < HID; j += 32) s += f[j] * w[j];
        #pragma unroll
        for (int o = 16; o > 0; o >>= 1) s += __shfl_xor_sync(0xffffffffu, s, o);
        if (lane == 0) outputs[n * OUTC + warp] = s + b4[warp];
    } else {
        const int l = blockIdx.x - NBATCH;
        const float* __restrict__ f = fr_all + (size_t)l * (NBATCH * HID);
        __shared__ float sh[320];
        float s = 0.f;
        for (int idx = threadIdx.x; idx < NBATCH * HID; idx += 320) s += f[idx];
        sh[threadIdx.x] = s;
        __syncthreads();
        if (threadIdx.x < 64){
            float v = sh[threadIdx.x];
            for (int o = threadIdx.x + 64; o < 320; o += 64) v += sh[o];
            sh[threadIdx.x] = v;
        }
        __syncthreads();
        if (threadIdx.x == 0){
            float v = 0.f;
            for (int o = 0; o < 64; ++o) v += sh[o];
            out3[l] = v * (1.f / (float)(NBATCH * HID));
        }
    }
}

// ---------------------------------------------------------------------------
// Launch: serial main chain; split_kernel overlapped on side stream.
// ---------------------------------------------------------------------------
extern "C" void kernel_launch(void* const* d_in, const int* in_sizes, int n_in,
                              void* d_out, int out_size)
{
    const float* x     = (const float*)d_in[0];
    const float* W1    = (const float*)d_in[1];
    const float* b1    = (const float*)d_in[2];
    const float* W2    = (const float*)d_in[3];
    const float* b2    = (const float*)d_in[4];
    const float* W3    = (const float*)d_in[5];
    const float* b3    = (const float*)d_in[6];
    const float* W4    = (const float*)d_in[7];
    const float* b4    = (const float*)d_in[8];
    const float* mask1 = (const float*)d_in[9];
    const float* mask2 = (const float*)d_in[10];
    const float* mask3 = (const float*)d_in[11];

    float* out     = (float*)d_out;
    float* outputs = out;
    float* fr1     = out + NBATCH * OUTC;
    float* fr2     = fr1 + NBATCH * HID;
    float* fr3     = fr2 + NBATCH * HID;
    float* lfr     = fr3 + NBATCH * HID;

    static cudaStream_t sB = nullptr;
    static cudaEvent_t evF, evS;
    if (!sB){
        cudaStreamCreateWithFlags(&sB, cudaStreamNonBlocking);
        cudaEventCreateWithFlags(&evF, cudaEventDisableTiming);
        cudaEventCreateWithFlags(&evS, cudaEventDisableTiming);
        cudaFuncSetAttribute(gemm_bf16, cudaFuncAttributeMaxDynamicSharedMemorySize, GEMM_SMEM);
    }

    dim3 gemm_grid(HID / BN, T_STEPS);   // (4, 784)
    dim3 rec_grid(NBATCH, HID / 128);
    dim3 mb_grid(NWORDS, 3);

    // Fork: weight split on side stream (needed only by GEMM-1)
    cudaEventRecord(evF, 0);
    cudaStreamWaitEvent(sB, evF, 0);
    split_kernel<<<(HID*HID + 255)/256, 256, 0, sB>>>(W2, W3);
    cudaEventRecord(evS, sB);

    maskbits_kernel<<<mb_grid, HID>>>(mask1, mask2, mask3);
    layer1_kernel<<<rec_grid, 128>>>(x, W1, b1, fr1);
    cudaStreamWaitEvent(0, evS, 0);   // join before GEMM-1
    gemm_bf16<<<gemm_grid, 256, GEMM_SMEM>>>(0);
    layerR_kernel<<<rec_grid, 128>>>(b2, fr2, 1, 2);
    gemm_bf16<<<gemm_grid, 256, GEMM_SMEM>>>(1);
    layerR_kernel<<<rec_grid, 128>>>(b3, fr3, 2, 3);
    tail_kernel<<<NBATCH + 3, 320>>>(fr1, W4, b4, outputs, lfr);
}

// round 16
// speedup vs baseline: 1.0475x; 1.0475x over previous
#include <cuda_runtime.h>
#include <cuda_bf16.h>
#include <cstdint>
#include <cstddef>

// Problem constants
#define T_STEPS 784
#define NBATCH  128
#define HID     512
#define OUTC    10
#define DECAY   0.2f
#define THRESH  0.5f
#define KDIM    512

// GEMM tiling (proven R13 config: 128x128, BK=64, 2 CTAs/SM)
#define BM 128
#define BN 128
#define BK 64
#define ROWB 144u              // smem bytes per row: 64 bf16 (128B) + 16B pad
#define TILEB (128u * ROWB)    // 18432 B
#define STAGEB (3u * TILEB)    // A + Bh + Bl per stage
#define GEMM_SMEM (2u * STAGEB)

// Recurrence pipelining
#define UNR 16                 // 784 = 49 * 16
#define NBLK (T_STEPS / UNR)   // 49
#define NWORDS 25              // ceil(784/32)

// Packed spikes: 512 bits per (t,n) row = 16 words = 64 bytes
#define WPR 16
#define SEQ_ELEMS ((size_t)T_STEPS * NBATCH * HID)
__device__ uint32_t g_S1p[(size_t)T_STEPS * NBATCH * WPR];
__device__ uint32_t g_S2p[(size_t)T_STEPS * NBATCH * WPR];
__device__ float    g_C  [SEQ_ELEMS];        // GEMM output [t][n][j] fp32 dense
__device__ __nv_bfloat16 g_W2h[HID*HID], g_W2l[HID*HID];
__device__ __nv_bfloat16 g_W3h[HID*HID], g_W3l[HID*HID];
__device__ uint32_t g_mkb[3][NWORDS * HID];  // bit-packed masks

// ---------------------------------------------------------------------------
// PTX helpers
// ---------------------------------------------------------------------------
__device__ __forceinline__ uint32_t smem_u32(const void* p){
    uint32_t a;
    asm("{ .reg .u64 t; cvta.to.shared.u64 t, %1; cvt.u32.u64 %0, t; }" : "=r"(a) : "l"(p));
    return a;
}
__device__ __forceinline__ void cp16(uint32_t saddr, const void* gaddr){
    asm volatile("cp.async.cg.shared.global [%0], [%1], 16;" :: "r"(saddr), "l"(gaddr));
}
__device__ __forceinline__ void ldsm4(uint32_t* r, uint32_t addr){
    asm volatile("ldmatrix.sync.aligned.m8n8.x4.shared.b16 {%0,%1,%2,%3}, [%4];"
        : "=r"(r[0]), "=r"(r[1]), "=r"(r[2]), "=r"(r[3]) : "r"(addr));
}
__device__ __forceinline__ void mma_bf16(float* c, const uint32_t* a, const uint32_t* b){
    asm volatile(
        "mma.sync.aligned.m16n8k16.row.col.f32.bf16.bf16.f32 "
        "{%0,%1,%2,%3}, {%4,%5,%6,%7}, {%8,%9}, {%0,%1,%2,%3};"
        : "+f"(c[0]), "+f"(c[1]), "+f"(c[2]), "+f"(c[3])
        : "r"(a[0]), "r"(a[1]), "r"(a[2]), "r"(a[3]), "r"(b[0]), "r"(b[1]));
}

// ---------------------------------------------------------------------------
// Weight split: W -> hi(bf16) + lo(bf16)
// ---------------------------------------------------------------------------
__global__ void split_kernel(const float* __restrict__ W2, const float* __restrict__ W3){
    int idx = blockIdx.x * blockDim.x + threadIdx.x;
    if (idx < HID * HID){
        float w = W2[idx];
        __nv_bfloat16 h = __float2bfloat16(w);
        g_W2h[idx] = h;
        g_W2l[idx] = __float2bfloat16(w - __bfloat162float(h));
        w = W3[idx];
        h = __float2bfloat16(w);
        g_W3h[idx] = h;
        g_W3l[idx] = __float2bfloat16(w - __bfloat162float(h));
    }
}

// ---------------------------------------------------------------------------
// Mask bit-pack: [H][T] floats -> [NWORDS][H] words.
// lsel: which mask to pack (0/1/2) — lets the launch split l=0 vs l=1,2.
// ---------------------------------------------------------------------------
__global__ void maskbits_kernel(const float* __restrict__ m1,
                                const float* __restrict__ m2,
                                const float* __restrict__ m3,
                                int lbase)
{
    const int w = blockIdx.x;
    const int l = lbase + (int)blockIdx.y;
    const int j = threadIdx.x;
    const float* __restrict__ src = (l == 0) ? m1 : (l == 1) ? m2 : m3;
    uint32_t bits = 0;
    #pragma unroll
    for (int b = 0; b < 32; ++b){
        const int t = w * 32 + b;
        if (t < T_STEPS && src[(size_t)j * T_STEPS + t] != 0.f) bits |= (1u << b);
    }
    g_mkb[l][w * HID + j] = bits;
}

// ---------------------------------------------------------------------------
// Layer-1 recurrence (R13 form)
// ---------------------------------------------------------------------------
__global__ void layer1_kernel(const float* __restrict__ x,
                              const float* __restrict__ W1,
                              const float* __restrict__ b1,
                              float* __restrict__ fr1)
{
    const int n = blockIdx.x;
    const int i = blockIdx.y * 128 + threadIdx.x;
    const int lane = threadIdx.x & 31;
    const float w = W1[i];
    const float b = b1[i];
    const float* __restrict__ xr = x + (size_t)n * T_STEPS;
    const uint32_t* __restrict__ mkb = g_mkb[0];
    uint32_t* __restrict__ pOut = g_S1p + (size_t)n * WPR
                                + (blockIdx.y * 4) + (threadIdx.x >> 5);
    const size_t pstr = (size_t)NBATCH * WPR;

    uint32_t mcur = mkb[i];
    uint32_t mnxt = mkb[HID + i];

    float xb[2][UNR];
    #pragma unroll
    for (int u = 0; u < UNR; ++u) xb[0][u] = xr[u];

    float mem = 0.f, spike = 0.f, ss = 0.f;
    for (int tc = 0; tc < NBLK; ++tc){
        const int cur = tc & 1, nxt = cur ^ 1;
        const int tb = tc * UNR;
        if (tc + 1 < NBLK){
            #pragma unroll
            for (int u = 0; u < UNR; ++u) xb[nxt][u] = xr[tb + UNR + u];
        }
        const uint32_t bits16 = (tc & 1) ? (mcur >> 16) : mcur;
        #pragma unroll
        for (int u = 0; u < UNR; ++u){
            const bool on = (bits16 >> u) & 1u;
            const float dec = (spike != 0.f) ? 0.f : mem * DECAY;
            const float nm = dec + xb[cur][u] * w + b;
            if (on) mem = nm;
            const float spk = (mem > THRESH && on) ? 1.f : 0.f;
            const unsigned bal = __ballot_sync(0xffffffffu, spk != 0.f);
            if (lane == 0) pOut[(size_t)(tb + u) * pstr] = bal;
            ss += spk;
            spike = spk;
        }
        if (tc & 1){
            mcur = mnxt;
            const int wi = (tc >> 1) + 2;
            if (wi < NWORDS) mnxt = mkb[wi * HID + i];
        }
    }
    fr1[n * HID + i] = ss * (1.f / (float)T_STEPS);
}

// ---------------------------------------------------------------------------
// bf16 HMMA GEMM — EXACT R13 version (batched bits in load_stage).
// ---------------------------------------------------------------------------
__global__ void __launch_bounds__(256, 2)
gemm_bf16(int which)
{
    extern __shared__ char smem[];
    const uint8_t* __restrict__ Ap = (const uint8_t*)(which ? g_S2p : g_S1p);
    const __nv_bfloat16* __restrict__ Bh = which ? g_W3h : g_W2h;
    const __nv_bfloat16* __restrict__ Bl = which ? g_W3l : g_W2l;

    const uint32_t sb = smem_u32(smem);
    const int tid  = threadIdx.x;
    const int lane = tid & 31;
    const int wrp  = tid >> 5;
    const int wm   = wrp & 1;
    const int wn   = wrp >> 1;
    const int n0 = blockIdx.x * BN;
    const int m0 = blockIdx.y * BM;

    auto load_stage = [&](int st, int c){
        const uint32_t base = sb + (uint32_t)st * STAGEB;
        char* abase = smem + (size_t)st * STAGEB;
        uint8_t bitsArr[4];
        #pragma unroll
        for (int i = 0; i < 4; ++i){
            const int q   = tid + 256 * i;
            const int row = q >> 3;
            const int kc  = q & 7;
            bitsArr[i] = __ldg(Ap + (size_t)(m0 + row) * 64 + (size_t)c * 8 + kc);
        }
        #pragma unroll
        for (int i = 0; i < 4; ++i){
            const int q   = tid + 256 * i;
            const int row = q >> 3;
            const int kc  = q & 7;
            const uint32_t soff = (uint32_t)row * ROWB + (uint32_t)kc * 16u;
            const size_t gk = (size_t)c * BK + (size_t)kc * 8;
            cp16(base + TILEB + soff,     Bh + (size_t)(n0 + row) * KDIM + gk);
            cp16(base + 2u*TILEB + soff,  Bl + (size_t)(n0 + row) * KDIM + gk);
        }
        #pragma unroll
        for (int i = 0; i < 4; ++i){
            const int q   = tid + 256 * i;
            const int row = q >> 3;
            const int kc  = q & 7;
            const uint32_t soff = (uint32_t)row * ROWB + (uint32_t)kc * 16u;
            const uint8_t bits = bitsArr[i];
            uint4 v;
            v.x = ((bits &   1u) ? 0x3F80u : 0u) | ((bits &   2u) ? 0x3F800000u : 0u);
            v.y = ((bits &   4u) ? 0x3F80u : 0u) | ((bits &   8u) ? 0x3F800000u : 0u);
            v.z = ((bits &  16u) ? 0x3F80u : 0u) | ((bits &  32u) ? 0x3F800000u : 0u);
            v.w = ((bits &  64u) ? 0x3F80u : 0u) | ((bits & 128u) ? 0x3F800000u : 0u);
            *(uint4*)(abase + soff) = v;
        }
        asm volatile("cp.async.commit_group;" ::: "memory");
    };

    float acc[4][4][4];
    #pragma unroll
    for (int mi = 0; mi < 4; ++mi)
        #pragma unroll
        for (int ni = 0; ni < 4; ++ni)
            #pragma unroll
            for (int q = 0; q < 4; ++q) acc[mi][ni][q] = 0.f;

    const uint32_t aOff = (uint32_t)(wm * 64 + (lane & 15)) * ROWB
                        + (uint32_t)((lane >> 4) << 3) * 2u;
    const uint32_t bOff = (uint32_t)(wn * 32 + ((lane >> 4) << 3) + (lane & 7)) * ROWB
                        + (uint32_t)(((lane >> 3) & 1) << 4);

    load_stage(0, 0);

    const int NC = KDIM / BK;   // 8
    for (int c = 0; c < NC; ++c){
        if (c + 1 < NC){
            load_stage((c + 1) & 1, c + 1);
            asm volatile("cp.async.wait_group 1;" ::: "memory");
        } else {
            asm volatile("cp.async.wait_group 0;" ::: "memory");
        }
        __syncthreads();

        const uint32_t base = sb + (uint32_t)(c & 1) * STAGEB;
        const uint32_t aB = base + aOff;
        const uint32_t hB = base + TILEB + bOff;
        const uint32_t lB = base + 2u*TILEB + bOff;

        #pragma unroll
        for (int k16 = 0; k16 < 4; ++k16){
            uint32_t a[4][4], bh[2][4], bl[2][4];
            #pragma unroll
            for (int mi = 0; mi < 4; ++mi)
                ldsm4(a[mi], aB + (uint32_t)(mi * 16) * ROWB + (uint32_t)k16 * 32u);
            #pragma unroll
            for (int p = 0; p < 2; ++p){
                ldsm4(bh[p], hB + (uint32_t)(p * 16) * ROWB + (uint32_t)k16 * 32u);
                ldsm4(bl[p], lB + (uint32_t)(p * 16) * ROWB + (uint32_t)k16 * 32u);
            }
            #pragma unroll
            for (int mi = 0; mi < 4; ++mi)
                #pragma unroll
                for (int ni = 0; ni < 4; ++ni){
                    mma_bf16(acc[mi][ni], a[mi], &bh[ni >> 1][(ni & 1) * 2]);
                    mma_bf16(acc[mi][ni], a[mi], &bl[ni >> 1][(ni & 1) * 2]);
                }
        }
        __syncthreads();
    }

    const int rbase = m0 + wm * 64 + (lane >> 2);
    const int cbase = n0 + wn * 32 + (lane & 3) * 2;
    #pragma unroll
    for (int mi = 0; mi < 4; ++mi){
        #pragma unroll
        for (int ni = 0; ni < 4; ++ni){
            float* p0 = g_C + (size_t)(rbase + mi * 16) * HID + cbase + ni * 8;
            float* p1 = p0 + 8 * HID;
            *(float2*)p0 = make_float2(acc[mi][ni][0], acc[mi][ni][1]);
            *(float2*)p1 = make_float2(acc[mi][ni][2], acc[mi][ni][3]);
        }
    }
}

// ---------------------------------------------------------------------------
// Layer-2/3 recurrence (R13 form: 3-buffer 2-ahead prefetch)
// ---------------------------------------------------------------------------
__global__ void layerR_kernel(const float* __restrict__ bvec,
                              float* __restrict__ fr,
                              int maskSel, int layer)
{
    const int n = blockIdx.x;
    const int j = blockIdx.y * 128 + threadIdx.x;
    const int lane = threadIdx.x & 31;
    const float bj = bvec[j];
    const uint32_t* __restrict__ mkb = g_mkb[maskSel];
    const size_t cstr = (size_t)NBATCH * HID;
    const float* __restrict__ cPtr = g_C + (size_t)n * HID + j;
    uint32_t* __restrict__ pOut = g_S2p + (size_t)n * WPR
                                + (blockIdx.y * 4) + (threadIdx.x >> 5);
    const size_t pstr = (size_t)NBATCH * WPR;

    uint32_t mcur = mkb[j];
    uint32_t mnxt = mkb[HID + j];

    float cb[3][UNR];
    #pragma unroll
    for (int u = 0; u < UNR; ++u) cb[0][u] = cPtr[(size_t)u * cstr];
    #pragma unroll
    for (int u = 0; u < UNR; ++u) cb[1][u] = cPtr[(size_t)(UNR + u) * cstr];

    float mem = 0.f, spike = 0.f, ss = 0.f;
    #pragma unroll 3
    for (int tc = 0; tc < NBLK; ++tc){
        const int s0 = tc % 3;
        const int tb = tc * UNR;
        if (tc + 2 < NBLK){
            const int s2 = (tc + 2) % 3;
            #pragma unroll
            for (int u = 0; u < UNR; ++u)
                cb[s2][u] = cPtr[(size_t)(tb + 2 * UNR + u) * cstr];
        }
        const uint32_t bits16 = (tc & 1) ? (mcur >> 16) : mcur;
        #pragma unroll
        for (int u = 0; u < UNR; ++u){
            const bool on = (bits16 >> u) & 1u;
            const float dec = (spike != 0.f) ? 0.f : mem * DECAY;
            const float nm = dec + cb[s0][u] + bj;
            if (on) mem = nm;
            const float spk = (mem > THRESH && on) ? 1.f : 0.f;
            if (layer == 2){
                const unsigned bal = __ballot_sync(0xffffffffu, spk != 0.f);
                if (lane == 0) pOut[(size_t)(tb + u) * pstr] = bal;
            }
            ss += spk;
            spike = spk;
        }
        if (tc & 1){
            mcur = mnxt;
            const int wi = (tc >> 1) + 2;
            if (wi < NWORDS) mnxt = mkb[wi * HID + j];
        }
    }
    fr[n * HID + j] = ss * (1.f / (float)T_STEPS);
}

// ---------------------------------------------------------------------------
// Fused head + layer_fr kernel.
// ---------------------------------------------------------------------------
__global__ void tail_kernel(const float* __restrict__ fr_all,
                            const float* __restrict__ W4,
                            const float* __restrict__ b4,
                            float* __restrict__ outputs,
                            float* __restrict__ out3)
{
    if (blockIdx.x < NBATCH){
        const int n = blockIdx.x;
        const int warp = threadIdx.x >> 5;
        const int lane = threadIdx.x & 31;
        if (warp >= OUTC) return;
        const float* __restrict__ f = fr_all + 2 * (NBATCH * HID) + (size_t)n * HID;
        const float* __restrict__ w = W4 + (size_t)warp * HID;
        float s = 0.f;
        for (int j = lane; j < HID; j += 32) s += f[j] * w[j];
        #pragma unroll
        for (int o = 16; o > 0; o >>= 1) s += __shfl_xor_sync(0xffffffffu, s, o);
        if (lane == 0) outputs[n * OUTC + warp] = s + b4[warp];
    } else {
        const int l = blockIdx.x - NBATCH;
        const float* __restrict__ f = fr_all + (size_t)l * (NBATCH * HID);
        __shared__ float sh[320];
        float s = 0.f;
        for (int idx = threadIdx.x; idx < NBATCH * HID; idx += 320) s += f[idx];
        sh[threadIdx.x] = s;
        __syncthreads();
        if (threadIdx.x < 64){
            float v = sh[threadIdx.x];
            for (int o = threadIdx.x + 64; o < 320; o += 64) v += sh[o];
            sh[threadIdx.x] = v;
        }
        __syncthreads();
        if (threadIdx.x == 0){
            float v = 0.f;
            for (int o = 0; o < 64; ++o) v += sh[o];
            out3[l] = v * (1.f / (float)(NBATCH * HID));
        }
    }
}

// ---------------------------------------------------------------------------
// Launch: serial main chain; split_kernel + masks 2/3 packing on side stream.
// ---------------------------------------------------------------------------
extern "C" void kernel_launch(void* const* d_in, const int* in_sizes, int n_in,
                              void* d_out, int out_size)
{
    const float* x     = (const float*)d_in[0];
    const float* W1    = (const float*)d_in[1];
    const float* b1    = (const float*)d_in[2];
    const float* W2    = (const float*)d_in[3];
    const float* b2    = (const float*)d_in[4];
    const float* W3    = (const float*)d_in[5];
    const float* b3    = (const float*)d_in[6];
    const float* W4    = (const float*)d_in[7];
    const float* b4    = (const float*)d_in[8];
    const float* mask1 = (const float*)d_in[9];
    const float* mask2 = (const float*)d_in[10];
    const float* mask3 = (const float*)d_in[11];

    float* out     = (float*)d_out;
    float* outputs = out;
    float* fr1     = out + NBATCH * OUTC;
    float* fr2     = fr1 + NBATCH * HID;
    float* fr3     = fr2 + NBATCH * HID;
    float* lfr     = fr3 + NBATCH * HID;

    static cudaStream_t sB = nullptr;
    static cudaEvent_t evF, evS;
    if (!sB){
        cudaStreamCreateWithFlags(&sB, cudaStreamNonBlocking);
        cudaEventCreateWithFlags(&evF, cudaEventDisableTiming);
        cudaEventCreateWithFlags(&evS, cudaEventDisableTiming);
        cudaFuncSetAttribute(gemm_bf16, cudaFuncAttributeMaxDynamicSharedMemorySize, GEMM_SMEM);
    }

    dim3 gemm_grid(HID / BN, T_STEPS);   // (4, 784)
    dim3 rec_grid(NBATCH, HID / 128);

    // Fork: weight split + masks 2/3 pack on side stream (needed from GEMM-1 /
    // layerR on). Critical path keeps only mask-1 packing before layer1.
    cudaEventRecord(evF, 0);
    cudaStreamWaitEvent(sB, evF, 0);
    split_kernel<<<(HID*HID + 255)/256, 256, 0, sB>>>(W2, W3);
    maskbits_kernel<<<dim3(NWORDS, 2), HID, 0, sB>>>(mask1, mask2, mask3, 1);
    cudaEventRecord(evS, sB);

    maskbits_kernel<<<dim3(NWORDS, 1), HID>>>(mask1, mask2, mask3, 0);
    layer1_kernel<<<rec_grid, 128>>>(x, W1, b1, fr1);
    cudaStreamWaitEvent(0, evS, 0);   // join before GEMM-1 (also covers masks 2/3)
    gemm_bf16<<<gemm_grid, 256, GEMM_SMEM>>>(0);
    layerR_kernel<<<rec_grid, 128>>>(b2, fr2, 1, 2);
    gemm_bf16<<<gemm_grid, 256, GEMM_SMEM>>>(1);
    layerR_kernel<<<rec_grid, 128>>>(b3, fr3, 2, 3);
    tail_kernel<<<NBATCH + 3, 320>>>(fr1, W4, b4, outputs, lfr);
}